// round 8
// baseline (speedup 1.0000x reference)
#include <cuda_runtime.h>
#include <math.h>

// Problem constants
#define MM    96      // MMAX
#define LLM   96      // LMAX
#define TLAT  255     // NLAT = 4*64-1
#define BC    256     // B*C = 4*64
#define NPIX  49152   // 12 * 64^2

typedef unsigned long long ull;

// ---- f32x2 packed math helpers (Blackwell FFMA2) --------------------------
__device__ __forceinline__ ull pack2(float lo, float hi) {
    ull r; asm("mov.b64 %0, {%1, %2};" : "=l"(r) : "f"(lo), "f"(hi)); return r;
}
__device__ __forceinline__ void unpack2(ull v, float& lo, float& hi) {
    asm("mov.b64 {%0, %1}, %2;" : "=f"(lo), "=f"(hi) : "l"(v));
}
__device__ __forceinline__ ull fma2(ull a, ull b, ull c) {
    ull d; asm("fma.rn.f32x2 %0, %1, %2, %3;" : "=l"(d) : "l"(a), "l"(b), "l"(c)); return d;
}

// Scratch
__device__ float  g_re[BC * MM * TLAT];       // [bc][m][t]
__device__ float  g_im[BC * MM * TLAT];
__device__ float2 g_xt[MM * LLM * BC];        // [m][l][bc] (re,im)

// ---------------------------------------------------------------------------
// Kernel T: transpose x (bc,l,m) -> xt (m,l,bc) as float2 (re,im).
// Grid: (l=96, mTile=3, bcTile=8), Block: (32,8).
// ---------------------------------------------------------------------------
__global__ __launch_bounds__(256)
void transpose_kernel(const float* __restrict__ xr, const float* __restrict__ xi)
{
    const int l   = blockIdx.x;
    const int mt  = blockIdx.y * 32;
    const int bct = blockIdx.z * 32;

    __shared__ float2 tile[32][33];

    const int x = threadIdx.x, y = threadIdx.y;
    #pragma unroll
    for (int i = 0; i < 4; ++i) {
        const int bc = bct + y + 8 * i;
        const int m  = mt + x;
        const int g  = (bc * LLM + l) * MM + m;   // coalesced along m
        tile[y + 8 * i][x] = make_float2(xr[g], xi[g]);
    }
    __syncthreads();
    #pragma unroll
    for (int i = 0; i < 4; ++i) {
        const int m  = mt + y + 8 * i;
        const int bc = bct + x;
        g_xt[((size_t)m * LLM + l) * BC + bc] = tile[x][y + 8 * i];  // coalesced along bc
    }
}

// ---------------------------------------------------------------------------
// Kernel A: batched register-tiled GEMM per m:
//   C[k, bc] = sum_l pct[m][l][k] * x[m][l][bc]   (complex x, real P)
// then phase-rotate by exp(i*off[k,m]) and scale by 2; store [bc][m][k].
// Block: 256 thr, tile 128 k x 64 bc; thread tile 8k x 4bc (f32x2 accum).
// Grid: (m=96, kblk=2, bcblk=4).
// ---------------------------------------------------------------------------
__global__ __launch_bounds__(256)
void legendre_gemm_kernel(const float* __restrict__ pct,
                          const float* __restrict__ off)
{
    const int m      = blockIdx.x;
    const int kbase  = blockIdx.y * 128;
    const int bcbase = blockIdx.z * 64;
    const int tid    = threadIdx.x;
    const int tx     = tid & 15;   // bc group (4 bc each)
    const int ty     = tid >> 4;   // k group  (8 k each)

    __shared__ __align__(16) float  sP[16][128];
    __shared__ __align__(16) float2 sX[16][64];

    ull acc[8][4];
    #pragma unroll
    for (int ki = 0; ki < 8; ++ki)
        #pragma unroll
        for (int bi = 0; bi < 4; ++bi) acc[ki][bi] = 0ull;

    for (int l0 = 0; l0 < LLM; l0 += 16) {
        __syncthreads();
        // stage P: 16 x 128 floats
        #pragma unroll
        for (int i = 0; i < 8; ++i) {
            const int idx = tid + i * 256;
            const int l  = idx >> 7;
            const int kk = idx & 127;
            int k = kbase + kk; if (k > TLAT - 1) k = TLAT - 1;  // clamp (dup, unused)
            sP[l][kk] = pct[((size_t)m * LLM + (l0 + l)) * TLAT + k];
        }
        // stage X: 16 x 64 float2
        #pragma unroll
        for (int i = 0; i < 4; ++i) {
            const int idx = tid + i * 256;
            const int l  = idx >> 6;
            const int bb = idx & 63;
            sX[l][bb] = g_xt[((size_t)m * LLM + (l0 + l)) * BC + bcbase + bb];
        }
        __syncthreads();

        #pragma unroll 4
        for (int l = 0; l < 16; ++l) {
            const float4 pA = *(const float4*)&sP[l][ty * 8];
            const float4 pB = *(const float4*)&sP[l][ty * 8 + 4];
            const ulonglong2 xA = *(const ulonglong2*)&sX[l][tx * 4];
            const ulonglong2 xB = *(const ulonglong2*)&sX[l][tx * 4 + 2];
            const ull xv0 = xA.x, xv1 = xA.y, xv2 = xB.x, xv3 = xB.y;
            ull pp;
            pp = pack2(pA.x, pA.x);
            acc[0][0]=fma2(xv0,pp,acc[0][0]); acc[0][1]=fma2(xv1,pp,acc[0][1]);
            acc[0][2]=fma2(xv2,pp,acc[0][2]); acc[0][3]=fma2(xv3,pp,acc[0][3]);
            pp = pack2(pA.y, pA.y);
            acc[1][0]=fma2(xv0,pp,acc[1][0]); acc[1][1]=fma2(xv1,pp,acc[1][1]);
            acc[1][2]=fma2(xv2,pp,acc[1][2]); acc[1][3]=fma2(xv3,pp,acc[1][3]);
            pp = pack2(pA.z, pA.z);
            acc[2][0]=fma2(xv0,pp,acc[2][0]); acc[2][1]=fma2(xv1,pp,acc[2][1]);
            acc[2][2]=fma2(xv2,pp,acc[2][2]); acc[2][3]=fma2(xv3,pp,acc[2][3]);
            pp = pack2(pA.w, pA.w);
            acc[3][0]=fma2(xv0,pp,acc[3][0]); acc[3][1]=fma2(xv1,pp,acc[3][1]);
            acc[3][2]=fma2(xv2,pp,acc[3][2]); acc[3][3]=fma2(xv3,pp,acc[3][3]);
            pp = pack2(pB.x, pB.x);
            acc[4][0]=fma2(xv0,pp,acc[4][0]); acc[4][1]=fma2(xv1,pp,acc[4][1]);
            acc[4][2]=fma2(xv2,pp,acc[4][2]); acc[4][3]=fma2(xv3,pp,acc[4][3]);
            pp = pack2(pB.y, pB.y);
            acc[5][0]=fma2(xv0,pp,acc[5][0]); acc[5][1]=fma2(xv1,pp,acc[5][1]);
            acc[5][2]=fma2(xv2,pp,acc[5][2]); acc[5][3]=fma2(xv3,pp,acc[5][3]);
            pp = pack2(pB.z, pB.z);
            acc[6][0]=fma2(xv0,pp,acc[6][0]); acc[6][1]=fma2(xv1,pp,acc[6][1]);
            acc[6][2]=fma2(xv2,pp,acc[6][2]); acc[6][3]=fma2(xv3,pp,acc[6][3]);
            pp = pack2(pB.w, pB.w);
            acc[7][0]=fma2(xv0,pp,acc[7][0]); acc[7][1]=fma2(xv1,pp,acc[7][1]);
            acc[7][2]=fma2(xv2,pp,acc[7][2]); acc[7][3]=fma2(xv3,pp,acc[7][3]);
        }
    }

    // Epilogue: phase rotation + scale by 2, scalar stores (k-contig per thread)
    #pragma unroll
    for (int ki = 0; ki < 8; ++ki) {
        const int k = kbase + ty * 8 + ki;
        if (k >= TLAT) break;
        float sa, ca;
        sincosf(off[k * MM + m], &sa, &ca);
        #pragma unroll
        for (int bi = 0; bi < 4; ++bi) {
            float re, im;
            unpack2(acc[ki][bi], re, im);
            const int bc = bcbase + tx * 4 + bi;
            const size_t o = ((size_t)bc * MM + m) * TLAT + k;
            g_re[o] = 2.0f * (re * ca - im * sa);
            g_im[o] = 2.0f * (re * sa + im * ca);
        }
    }
}

// ---------------------------------------------------------------------------
// Kernel B: per-ring inverse real DFT (norm='forward', n % 4 == 0).
// Quarter-wave split + j-pairing (unchanged from best round).
// Grid: (bcChunk=64, t=255), Block: 32 threads.
// ---------------------------------------------------------------------------
__global__ __launch_bounds__(32)
void ring_idft_kernel(float* __restrict__ out)
{
    const int t   = blockIdx.y;
    const int bc0 = blockIdx.x * 4;
    const int tid = threadIdx.x;

    int n, roff;
    if (t <= 62)       { n = 4 * (t + 1); roff = 2 * t * (t + 1); }
    else if (t <= 191) { n = 256;         roff = 8064 + 256 * (t - 63); }
    else               { const int w = 255 - t; n = 4 * w; roff = NPIX - 2 * w * (w + 1); }

    const int nh   = n >> 1;
    const int n4   = n >> 2;
    const int kend = (nh - 1 < MM - 1) ? (nh - 1) : (MM - 1);
    const int kmax = (nh < MM - 1) ? nh : (MM - 1);

    __shared__ __align__(16) float sr4[MM * 4];
    __shared__ __align__(16) float si4[MM * 4];

    for (int idx = tid; idx < (kmax + 1) * 4; idx += 32) {
        const int mm = idx >> 2;
        const int b  = idx & 3;
        const size_t g = ((size_t)(bc0 + b) * MM + mm) * TLAT + t;
        sr4[idx] = g_re[g];
        si4[idx] = g_im[g];
    }
    __syncthreads();

    const int j0 = 2 * tid;
    if (j0 >= n4) return;
    const int j1 = j0 + 1;
    const bool a1 = (j1 < n4);

    ull U0a0, U0b0, U1a0, U1b0, U2a0, U2b0, U3a0, U3b0, V1a0, V1b0, V3a0, V3b0;
    ull U0a1, U0b1, U1a1, U1b1, U2a1, U2b1, U3a1, U3b1, V1a1, V1b1, V3a1, V3b1;

    {
        const ulonglong2 rp = *(const ulonglong2*)(sr4);
        const ull half = pack2(0.5f, 0.5f);
        U0a0 = fma2(rp.x, half, 0ull);
        U0b0 = fma2(rp.y, half, 0ull);
        U0a1 = U0a0; U0b1 = U0b0;
    }
    U1a0=U1b0=U2a0=U2b0=U3a0=U3b0=V1a0=V1b0=V3a0=V3b0=0ull;
    U1a1=U1b1=U2a1=U2b1=U3a1=U3b1=V1a1=V1b1=V3a1=V3b1=0ull;

    const float tstep = 6.283185307179586f / (float)n;
    float stc0, sts0, stc1, sts1;
    sincosf(tstep * (float)j0, &sts0, &stc0);
    sincosf(tstep * (float)j1, &sts1, &stc1);
    float ca = stc0, sa = sts0;
    float cb = stc1, sb = sts1;

    #define LOADK(K)                                                        \
        const ulonglong2 rp = *(const ulonglong2*)(sr4 + (K) * 4);          \
        const ulonglong2 ip = *(const ulonglong2*)(si4 + (K) * 4);

    #define ACC_U2(K, A0, B0, A1, B1)                                       \
    {                                                                       \
        LOADK(K)                                                            \
        {                                                                   \
            const ull cc = pack2(ca, ca), ns = pack2(-sa, -sa);             \
            A0 = fma2(rp.x, cc, A0); A0 = fma2(ip.x, ns, A0);               \
            B0 = fma2(rp.y, cc, B0); B0 = fma2(ip.y, ns, B0);               \
        }                                                                   \
        {                                                                   \
            const ull cc = pack2(cb, cb), ns = pack2(-sb, -sb);             \
            A1 = fma2(rp.x, cc, A1); A1 = fma2(ip.x, ns, A1);               \
            B1 = fma2(rp.y, cc, B1); B1 = fma2(ip.y, ns, B1);               \
        }                                                                   \
    }
    #define ACC_UV2(K, A0, B0, VA0, VB0, A1, B1, VA1, VB1)                  \
    {                                                                       \
        LOADK(K)                                                            \
        {                                                                   \
            const ull cc = pack2(ca, ca), ns = pack2(-sa, -sa), ss = pack2(sa, sa); \
            A0  = fma2(rp.x, cc, A0);  A0  = fma2(ip.x, ns, A0);            \
            B0  = fma2(rp.y, cc, B0);  B0  = fma2(ip.y, ns, B0);            \
            VA0 = fma2(rp.x, ss, VA0); VA0 = fma2(ip.x, cc, VA0);           \
            VB0 = fma2(rp.y, ss, VB0); VB0 = fma2(ip.y, cc, VB0);           \
        }                                                                   \
        {                                                                   \
            const ull cc = pack2(cb, cb), ns = pack2(-sb, -sb), ss = pack2(sb, sb); \
            A1  = fma2(rp.x, cc, A1);  A1  = fma2(ip.x, ns, A1);            \
            B1  = fma2(rp.y, cc, B1);  B1  = fma2(ip.y, ns, B1);            \
            VA1 = fma2(rp.x, ss, VA1); VA1 = fma2(ip.x, cc, VA1);           \
            VB1 = fma2(rp.y, ss, VB1); VB1 = fma2(ip.y, cc, VB1);           \
        }                                                                   \
    }
    #define ROT2()                                                          \
    {                                                                       \
        const float na = fmaf(ca, stc0, -sa * sts0);                        \
        const float ma = fmaf(sa, stc0,  ca * sts0);                        \
        ca = na; sa = ma;                                                   \
        const float nb = fmaf(cb, stc1, -sb * sts1);                        \
        const float mb = fmaf(sb, stc1,  cb * sts1);                        \
        cb = nb; sb = mb;                                                   \
    }

    int k = 1;
    for (; k + 3 <= kend; k += 4) {
        ACC_UV2(k,     U1a0,U1b0,V1a0,V1b0, U1a1,U1b1,V1a1,V1b1) ROT2()
        ACC_U2 (k + 1, U2a0,U2b0, U2a1,U2b1)                     ROT2()
        ACC_UV2(k + 2, U3a0,U3b0,V3a0,V3b0, U3a1,U3b1,V3a1,V3b1) ROT2()
        ACC_U2 (k + 3, U0a0,U0b0, U0a1,U0b1)                     ROT2()
    }
    for (; k <= kend; ++k) {
        const int r = k & 3;
        if (r == 1)      { ACC_UV2(k, U1a0,U1b0,V1a0,V1b0, U1a1,U1b1,V1a1,V1b1) }
        else if (r == 2) { ACC_U2 (k, U2a0,U2b0, U2a1,U2b1) }
        else if (r == 3) { ACC_UV2(k, U3a0,U3b0,V3a0,V3b0, U3a1,U3b1,V3a1,V3b1) }
        else             { ACC_U2 (k, U0a0,U0b0, U0a1,U0b1) }
        ROT2()
    }
    #undef LOADK
    #undef ACC_U2
    #undef ACC_UV2
    #undef ROT2

    float w[4] = {0.f, 0.f, 0.f, 0.f};
    if (nh < MM) {
        w[0] = 0.5f * sr4[nh * 4 + 0];
        w[1] = 0.5f * sr4[nh * 4 + 1];
        w[2] = 0.5f * sr4[nh * 4 + 2];
        w[3] = 0.5f * sr4[nh * 4 + 3];
    }

    float u0[2][4], u1[2][4], u2[2][4], u3[2][4], v1[2][4], v3[2][4];
    unpack2(U0a0, u0[0][0], u0[0][1]); unpack2(U0b0, u0[0][2], u0[0][3]);
    unpack2(U1a0, u1[0][0], u1[0][1]); unpack2(U1b0, u1[0][2], u1[0][3]);
    unpack2(U2a0, u2[0][0], u2[0][1]); unpack2(U2b0, u2[0][2], u2[0][3]);
    unpack2(U3a0, u3[0][0], u3[0][1]); unpack2(U3b0, u3[0][2], u3[0][3]);
    unpack2(V1a0, v1[0][0], v1[0][1]); unpack2(V1b0, v1[0][2], v1[0][3]);
    unpack2(V3a0, v3[0][0], v3[0][1]); unpack2(V3b0, v3[0][2], v3[0][3]);
    unpack2(U0a1, u0[1][0], u0[1][1]); unpack2(U0b1, u0[1][2], u0[1][3]);
    unpack2(U1a1, u1[1][0], u1[1][1]); unpack2(U1b1, u1[1][2], u1[1][3]);
    unpack2(U2a1, u2[1][0], u2[1][1]); unpack2(U2b1, u2[1][2], u2[1][3]);
    unpack2(U3a1, u3[1][0], u3[1][1]); unpack2(U3b1, u3[1][2], u3[1][3]);
    unpack2(V1a1, v1[1][0], v1[1][1]); unpack2(V1b1, v1[1][2], v1[1][3]);
    unpack2(V3a1, v3[1][0], v3[1][1]); unpack2(V3b1, v3[1][2], v3[1][3]);

    float y[2][4][4];
    #pragma unroll
    for (int jj = 0; jj < 2; ++jj) {
        #pragma unroll
        for (int b = 0; b < 4; ++b) {
            const float P  = u0[jj][b] + u2[jj][b];
            const float Md = u0[jj][b] - u2[jj][b];
            const float Cc = u1[jj][b] + u3[jj][b];
            const float Dd = v1[jj][b] - v3[jj][b];
            y[jj][0][b] = P + Cc;
            y[jj][1][b] = Md - Dd;
            y[jj][2][b] = P - Cc;
            y[jj][3][b] = Md + Dd;
        }
    }

    const size_t obase = (size_t)bc0 * NPIX + roff;
    if ((n4 & 1) == 0) {
        #pragma unroll
        for (int q = 0; q < 4; ++q) {
            #pragma unroll
            for (int b = 0; b < 4; ++b) {
                const float2 val = make_float2(y[0][q][b] + w[b],
                                               y[1][q][b] - w[b]);
                *(float2*)(out + obase + (size_t)b * NPIX + q * n4 + j0) = val;
            }
        }
    } else {
        #pragma unroll
        for (int q = 0; q < 4; ++q) {
            const int p0 = j0 + q * n4;
            const float sg0 = (p0 & 1) ? -1.0f : 1.0f;
            #pragma unroll
            for (int b = 0; b < 4; ++b)
                out[obase + (size_t)b * NPIX + p0] = fmaf(sg0, w[b], y[0][q][b]);
            if (a1) {
                const float sg1 = -sg0;
                #pragma unroll
                for (int b = 0; b < 4; ++b)
                    out[obase + (size_t)b * NPIX + p0 + 1] = fmaf(sg1, w[b], y[1][q][b]);
            }
        }
    }
}

// ---------------------------------------------------------------------------
extern "C" void kernel_launch(void* const* d_in, const int* in_sizes, int n_in,
                              void* d_out, int out_size)
{
    const float* xr  = (const float*)d_in[0];  // (4,64,96,96)
    const float* xi  = (const float*)d_in[1];  // (4,64,96,96)
    const float* pct = (const float*)d_in[2];  // (96,96,255)
    const float* off = (const float*)d_in[3];  // (255,96)
    float* out = (float*)d_out;                // (4,64,49152)

    {
        dim3 grid(LLM, 3, 8);          // (l, mTile, bcTile)
        transpose_kernel<<<grid, dim3(32, 8)>>>(xr, xi);
    }
    {
        dim3 grid(MM, 2, 4);           // (m, kblk, bcblk)
        legendre_gemm_kernel<<<grid, 256>>>(pct, off);
    }
    {
        dim3 grid(BC / 4, TLAT);       // 64 x 255
        ring_idft_kernel<<<grid, 32>>>(out);
    }
}

// round 9
// speedup vs baseline: 1.4335x; 1.4335x over previous
#include <cuda_runtime.h>
#include <math.h>

// Problem constants
#define MM    96      // MMAX
#define LLM   96      // LMAX
#define TLAT  255     // NLAT = 4*64-1
#define BC    256     // B*C = 4*64
#define NPIX  49152   // 12 * 64^2

typedef unsigned long long ull;

// ---- f32x2 packed math helpers ---------------------------------------------
__device__ __forceinline__ ull pack2(float lo, float hi) {
    ull r; asm("mov.b64 %0, {%1, %2};" : "=l"(r) : "f"(lo), "f"(hi)); return r;
}
__device__ __forceinline__ void unpack2(ull v, float& lo, float& hi) {
    asm("mov.b64 {%0, %1}, %2;" : "=f"(lo), "=f"(hi) : "l"(v));
}
__device__ __forceinline__ ull fma2(ull a, ull b, ull c) {
    ull d; asm("fma.rn.f32x2 %0, %1, %2, %3;" : "=l"(d) : "l"(a), "l"(b), "l"(c)); return d;
}

// Scratch: phase-rotated spectral coefficients, pre-scaled by 2 (irfft weight).
// Layout [bc][m][t].
__device__ float g_re[BC * MM * TLAT];
__device__ float g_im[BC * MM * TLAT];

// ---------------------------------------------------------------------------
// Kernel A with latitude mirror symmetry:
//   P_lm(-z) = (-1)^(l+m) P_lm(z);  ring t and 254-t have z -> -z.
// Accumulate E = sum_{l even} x_l P_l(k),  O = sum_{l odd} x_l P_l(k):
//   ring k      = E + O
//   ring 254-k  = (-1)^m (E - O)
// Thread: 2 ring-pairs (rp, rp+64) x 4 bc; FMA work is HALF of the direct sum.
// Grid: (m=96, bcChunk=32), Block: 128 threads.
// ---------------------------------------------------------------------------
__global__ __launch_bounds__(128)
void legendre_phase_kernel(const float* __restrict__ xr,
                           const float* __restrict__ xi,
                           const float* __restrict__ pct,
                           const float* __restrict__ off)
{
    const int m     = blockIdx.x;
    const int bc0   = blockIdx.y * 8;
    const int tid   = threadIdx.x;
    const int bcsub = (tid & 1) * 4;   // 0 or 4: which half of the 8 bc
    const int rp    = tid >> 1;        // 0..63
    const int kA    = rp;              // pair A: rings kA, 254-kA
    const int kB    = rp + 64;         // pair B: rings kB, 254-kB (kB=127 self-paired)

    __shared__ __align__(16) float2 sx[LLM * 8];   // (re,im), [l][b]

    for (int idx = tid; idx < LLM * 8; idx += 128) {
        const int l = idx >> 3;
        const int b = idx & 7;
        const int g = ((bc0 + b) * LLM + l) * MM + m;
        sx[idx] = make_float2(xr[g], xi[g]);
    }
    __syncthreads();

    ull EA[4], OA[4], EB[4], OB[4];
    #pragma unroll
    for (int b = 0; b < 4; ++b) { EA[b]=0ull; OA[b]=0ull; EB[b]=0ull; OB[b]=0ull; }

    const float* __restrict__ pm = pct + (size_t)m * LLM * TLAT;

    #pragma unroll 2
    for (int l = 0; l < LLM; l += 2) {
        {   // even l -> E
            const float pa = pm[(size_t)l * TLAT + kA];
            const float pb = pm[(size_t)l * TLAT + kB];
            const ulonglong2 v0 = *(const ulonglong2*)(sx + l * 8 + bcsub);
            const ulonglong2 v1 = *(const ulonglong2*)(sx + l * 8 + bcsub + 2);
            const ull ppa = pack2(pa, pa), ppb = pack2(pb, pb);
            EA[0]=fma2(v0.x,ppa,EA[0]); EA[1]=fma2(v0.y,ppa,EA[1]);
            EA[2]=fma2(v1.x,ppa,EA[2]); EA[3]=fma2(v1.y,ppa,EA[3]);
            EB[0]=fma2(v0.x,ppb,EB[0]); EB[1]=fma2(v0.y,ppb,EB[1]);
            EB[2]=fma2(v1.x,ppb,EB[2]); EB[3]=fma2(v1.y,ppb,EB[3]);
        }
        {   // odd l+1 -> O
            const int lo = l + 1;
            const float pa = pm[(size_t)lo * TLAT + kA];
            const float pb = pm[(size_t)lo * TLAT + kB];
            const ulonglong2 v0 = *(const ulonglong2*)(sx + lo * 8 + bcsub);
            const ulonglong2 v1 = *(const ulonglong2*)(sx + lo * 8 + bcsub + 2);
            const ull ppa = pack2(pa, pa), ppb = pack2(pb, pb);
            OA[0]=fma2(v0.x,ppa,OA[0]); OA[1]=fma2(v0.y,ppa,OA[1]);
            OA[2]=fma2(v1.x,ppa,OA[2]); OA[3]=fma2(v1.y,ppa,OA[3]);
            OB[0]=fma2(v0.x,ppb,OB[0]); OB[1]=fma2(v0.y,ppb,OB[1]);
            OB[2]=fma2(v1.x,ppb,OB[2]); OB[3]=fma2(v1.y,ppb,OB[3]);
        }
    }

    const float msign = (m & 1) ? -1.0f : 1.0f;

    // Emit one ring pair: k (E+O) and 254-k ((-1)^m (E-O))
    #define EMIT_PAIR(KK, EACC, OACC, SELF)                                  \
    {                                                                        \
        const int kk = (KK);                                                 \
        const int km = 254 - kk;                                             \
        float s1, c1s, s2, c2s;                                              \
        sincosf(off[kk * MM + m], &s1, &c1s);                                \
        sincosf(off[km * MM + m], &s2, &c2s);                                \
        _Pragma("unroll")                                                    \
        for (int b = 0; b < 4; ++b) {                                        \
            float er, ei, orr, oii;                                          \
            unpack2(EACC[b], er, ei);                                        \
            unpack2(OACC[b], orr, oii);                                      \
            const int bc = bc0 + bcsub + b;                                  \
            const size_t o1 = ((size_t)bc * MM + m) * TLAT + kk;             \
            const float r1 = er + orr, i1 = ei + oii;                        \
            g_re[o1] = 2.0f * (r1 * c1s - i1 * s1);                          \
            g_im[o1] = 2.0f * (r1 * s1 + i1 * c1s);                          \
            if (!(SELF)) {                                                   \
                const float r2 = msign * (er - orr), i2 = msign * (ei - oii);\
                const size_t o2 = ((size_t)bc * MM + m) * TLAT + km;         \
                g_re[o2] = 2.0f * (r2 * c2s - i2 * s2);                      \
                g_im[o2] = 2.0f * (r2 * s2 + i2 * c2s);                      \
            }                                                                \
        }                                                                    \
    }

    EMIT_PAIR(kA, EA, OA, false)
    EMIT_PAIR(kB, EB, OB, (kB == 127))
    #undef EMIT_PAIR
}

// ---------------------------------------------------------------------------
// Kernel B: per-ring inverse real DFT (norm='forward', n % 4 == 0).
// Quarter-wave split + j-pairing (unchanged from best round).
// Grid: (bcChunk=64, t=255), Block: 32 threads.
// ---------------------------------------------------------------------------
__global__ __launch_bounds__(32)
void ring_idft_kernel(float* __restrict__ out)
{
    const int t   = blockIdx.y;
    const int bc0 = blockIdx.x * 4;
    const int tid = threadIdx.x;

    int n, roff;
    if (t <= 62)       { n = 4 * (t + 1); roff = 2 * t * (t + 1); }
    else if (t <= 191) { n = 256;         roff = 8064 + 256 * (t - 63); }
    else               { const int w = 255 - t; n = 4 * w; roff = NPIX - 2 * w * (w + 1); }

    const int nh   = n >> 1;
    const int n4   = n >> 2;
    const int kend = (nh - 1 < MM - 1) ? (nh - 1) : (MM - 1);
    const int kmax = (nh < MM - 1) ? nh : (MM - 1);

    __shared__ __align__(16) float sr4[MM * 4];
    __shared__ __align__(16) float si4[MM * 4];

    for (int idx = tid; idx < (kmax + 1) * 4; idx += 32) {
        const int mm = idx >> 2;
        const int b  = idx & 3;
        const size_t g = ((size_t)(bc0 + b) * MM + mm) * TLAT + t;
        sr4[idx] = g_re[g];
        si4[idx] = g_im[g];
    }
    __syncthreads();

    const int j0 = 2 * tid;
    if (j0 >= n4) return;
    const int j1 = j0 + 1;
    const bool a1 = (j1 < n4);

    ull U0a0, U0b0, U1a0, U1b0, U2a0, U2b0, U3a0, U3b0, V1a0, V1b0, V3a0, V3b0;
    ull U0a1, U0b1, U1a1, U1b1, U2a1, U2b1, U3a1, U3b1, V1a1, V1b1, V3a1, V3b1;

    {
        const ulonglong2 rp = *(const ulonglong2*)(sr4);
        const ull half = pack2(0.5f, 0.5f);
        U0a0 = fma2(rp.x, half, 0ull);
        U0b0 = fma2(rp.y, half, 0ull);
        U0a1 = U0a0; U0b1 = U0b0;
    }
    U1a0=U1b0=U2a0=U2b0=U3a0=U3b0=V1a0=V1b0=V3a0=V3b0=0ull;
    U1a1=U1b1=U2a1=U2b1=U3a1=U3b1=V1a1=V1b1=V3a1=V3b1=0ull;

    const float tstep = 6.283185307179586f / (float)n;
    float stc0, sts0, stc1, sts1;
    sincosf(tstep * (float)j0, &sts0, &stc0);
    sincosf(tstep * (float)j1, &sts1, &stc1);
    float ca = stc0, sa = sts0;
    float cb = stc1, sb = sts1;

    #define LOADK(K)                                                        \
        const ulonglong2 rp = *(const ulonglong2*)(sr4 + (K) * 4);          \
        const ulonglong2 ip = *(const ulonglong2*)(si4 + (K) * 4);

    #define ACC_U2(K, A0, B0, A1, B1)                                       \
    {                                                                       \
        LOADK(K)                                                            \
        {                                                                   \
            const ull cc = pack2(ca, ca), ns = pack2(-sa, -sa);             \
            A0 = fma2(rp.x, cc, A0); A0 = fma2(ip.x, ns, A0);               \
            B0 = fma2(rp.y, cc, B0); B0 = fma2(ip.y, ns, B0);               \
        }                                                                   \
        {                                                                   \
            const ull cc = pack2(cb, cb), ns = pack2(-sb, -sb);             \
            A1 = fma2(rp.x, cc, A1); A1 = fma2(ip.x, ns, A1);               \
            B1 = fma2(rp.y, cc, B1); B1 = fma2(ip.y, ns, B1);               \
        }                                                                   \
    }
    #define ACC_UV2(K, A0, B0, VA0, VB0, A1, B1, VA1, VB1)                  \
    {                                                                       \
        LOADK(K)                                                            \
        {                                                                   \
            const ull cc = pack2(ca, ca), ns = pack2(-sa, -sa), ss = pack2(sa, sa); \
            A0  = fma2(rp.x, cc, A0);  A0  = fma2(ip.x, ns, A0);            \
            B0  = fma2(rp.y, cc, B0);  B0  = fma2(ip.y, ns, B0);            \
            VA0 = fma2(rp.x, ss, VA0); VA0 = fma2(ip.x, cc, VA0);           \
            VB0 = fma2(rp.y, ss, VB0); VB0 = fma2(ip.y, cc, VB0);           \
        }                                                                   \
        {                                                                   \
            const ull cc = pack2(cb, cb), ns = pack2(-sb, -sb), ss = pack2(sb, sb); \
            A1  = fma2(rp.x, cc, A1);  A1  = fma2(ip.x, ns, A1);            \
            B1  = fma2(rp.y, cc, B1);  B1  = fma2(ip.y, ns, B1);            \
            VA1 = fma2(rp.x, ss, VA1); VA1 = fma2(ip.x, cc, VA1);           \
            VB1 = fma2(rp.y, ss, VB1); VB1 = fma2(ip.y, cc, VB1);           \
        }                                                                   \
    }
    #define ROT2()                                                          \
    {                                                                       \
        const float na = fmaf(ca, stc0, -sa * sts0);                        \
        const float ma = fmaf(sa, stc0,  ca * sts0);                        \
        ca = na; sa = ma;                                                   \
        const float nb = fmaf(cb, stc1, -sb * sts1);                        \
        const float mb = fmaf(sb, stc1,  cb * sts1);                        \
        cb = nb; sb = mb;                                                   \
    }

    int k = 1;
    for (; k + 3 <= kend; k += 4) {
        ACC_UV2(k,     U1a0,U1b0,V1a0,V1b0, U1a1,U1b1,V1a1,V1b1) ROT2()
        ACC_U2 (k + 1, U2a0,U2b0, U2a1,U2b1)                     ROT2()
        ACC_UV2(k + 2, U3a0,U3b0,V3a0,V3b0, U3a1,U3b1,V3a1,V3b1) ROT2()
        ACC_U2 (k + 3, U0a0,U0b0, U0a1,U0b1)                     ROT2()
    }
    for (; k <= kend; ++k) {
        const int r = k & 3;
        if (r == 1)      { ACC_UV2(k, U1a0,U1b0,V1a0,V1b0, U1a1,U1b1,V1a1,V1b1) }
        else if (r == 2) { ACC_U2 (k, U2a0,U2b0, U2a1,U2b1) }
        else if (r == 3) { ACC_UV2(k, U3a0,U3b0,V3a0,V3b0, U3a1,U3b1,V3a1,V3b1) }
        else             { ACC_U2 (k, U0a0,U0b0, U0a1,U0b1) }
        ROT2()
    }
    #undef LOADK
    #undef ACC_U2
    #undef ACC_UV2
    #undef ROT2

    float w[4] = {0.f, 0.f, 0.f, 0.f};
    if (nh < MM) {
        w[0] = 0.5f * sr4[nh * 4 + 0];
        w[1] = 0.5f * sr4[nh * 4 + 1];
        w[2] = 0.5f * sr4[nh * 4 + 2];
        w[3] = 0.5f * sr4[nh * 4 + 3];
    }

    float u0[2][4], u1[2][4], u2[2][4], u3[2][4], v1[2][4], v3[2][4];
    unpack2(U0a0, u0[0][0], u0[0][1]); unpack2(U0b0, u0[0][2], u0[0][3]);
    unpack2(U1a0, u1[0][0], u1[0][1]); unpack2(U1b0, u1[0][2], u1[0][3]);
    unpack2(U2a0, u2[0][0], u2[0][1]); unpack2(U2b0, u2[0][2], u2[0][3]);
    unpack2(U3a0, u3[0][0], u3[0][1]); unpack2(U3b0, u3[0][2], u3[0][3]);
    unpack2(V1a0, v1[0][0], v1[0][1]); unpack2(V1b0, v1[0][2], v1[0][3]);
    unpack2(V3a0, v3[0][0], v3[0][1]); unpack2(V3b0, v3[0][2], v3[0][3]);
    unpack2(U0a1, u0[1][0], u0[1][1]); unpack2(U0b1, u0[1][2], u0[1][3]);
    unpack2(U1a1, u1[1][0], u1[1][1]); unpack2(U1b1, u1[1][2], u1[1][3]);
    unpack2(U2a1, u2[1][0], u2[1][1]); unpack2(U2b1, u2[1][2], u2[1][3]);
    unpack2(U3a1, u3[1][0], u3[1][1]); unpack2(U3b1, u3[1][2], u3[1][3]);
    unpack2(V1a1, v1[1][0], v1[1][1]); unpack2(V1b1, v1[1][2], v1[1][3]);
    unpack2(V3a1, v3[1][0], v3[1][1]); unpack2(V3b1, v3[1][2], v3[1][3]);

    float y[2][4][4];
    #pragma unroll
    for (int jj = 0; jj < 2; ++jj) {
        #pragma unroll
        for (int b = 0; b < 4; ++b) {
            const float P  = u0[jj][b] + u2[jj][b];
            const float Md = u0[jj][b] - u2[jj][b];
            const float Cc = u1[jj][b] + u3[jj][b];
            const float Dd = v1[jj][b] - v3[jj][b];
            y[jj][0][b] = P + Cc;
            y[jj][1][b] = Md - Dd;
            y[jj][2][b] = P - Cc;
            y[jj][3][b] = Md + Dd;
        }
    }

    const size_t obase = (size_t)bc0 * NPIX + roff;
    if ((n4 & 1) == 0) {
        #pragma unroll
        for (int q = 0; q < 4; ++q) {
            #pragma unroll
            for (int b = 0; b < 4; ++b) {
                const float2 val = make_float2(y[0][q][b] + w[b],
                                               y[1][q][b] - w[b]);
                *(float2*)(out + obase + (size_t)b * NPIX + q * n4 + j0) = val;
            }
        }
    } else {
        #pragma unroll
        for (int q = 0; q < 4; ++q) {
            const int p0 = j0 + q * n4;
            const float sg0 = (p0 & 1) ? -1.0f : 1.0f;
            #pragma unroll
            for (int b = 0; b < 4; ++b)
                out[obase + (size_t)b * NPIX + p0] = fmaf(sg0, w[b], y[0][q][b]);
            if (a1) {
                const float sg1 = -sg0;
                #pragma unroll
                for (int b = 0; b < 4; ++b)
                    out[obase + (size_t)b * NPIX + p0 + 1] = fmaf(sg1, w[b], y[1][q][b]);
            }
        }
    }
}

// ---------------------------------------------------------------------------
extern "C" void kernel_launch(void* const* d_in, const int* in_sizes, int n_in,
                              void* d_out, int out_size)
{
    const float* xr  = (const float*)d_in[0];  // (4,64,96,96)
    const float* xi  = (const float*)d_in[1];  // (4,64,96,96)
    const float* pct = (const float*)d_in[2];  // (96,96,255)
    const float* off = (const float*)d_in[3];  // (255,96)
    float* out = (float*)d_out;                // (4,64,49152)

    {
        dim3 grid(MM, BC / 8);     // 96 x 32
        legendre_phase_kernel<<<grid, 128>>>(xr, xi, pct, off);
    }
    {
        dim3 grid(BC / 4, TLAT);   // 64 x 255
        ring_idft_kernel<<<grid, 32>>>(out);
    }
}